// round 1
// baseline (speedup 1.0000x reference)
#include <cuda_runtime.h>

#define BN_TOT 2048          // B*N = 8*256
#define M_DIM  256
#define CIN    64
#define CMID   256
#define COUT   256
#define W2P    320           // w2 row pitch = CIN + CMID
#define KP     132           // k-major smem pitch (132%32=4 -> staggered banks; 132*4%16==0 -> float4 aligned)
#define K2P    65

// scratch (no allocation allowed): partial maxes per (bn, mtile) and v = zmax @ w2b^T
__device__ float g_zpart[BN_TOT * 2 * CMID];   // 4 MB
__device__ float g_v[BN_TOT * COUT];           // 2 MB

// ---------------------------------------------------------------------------
// K1: per (bn, mtile, dtile) compute z = x @ w1^T (128m x 128d, K=64),
//     then max over the 128 m rows, add bias, write partial max.
// ---------------------------------------------------------------------------
__global__ __launch_bounds__(256, 2)
void k1_gemm_max(const float* __restrict__ x, const float* __restrict__ w1,
                 const float* __restrict__ b1)
{
    __shared__ float s[2 * 32 * KP];           // 33792 B
    float* asT = s;                            // [32 k][128 m] pitch KP
    float* bsT = s + 32 * KP;                  // [32 k][128 d] pitch KP

    const int tid = threadIdx.x;
    const int tx = tid & 15, ty = tid >> 4;
    const int dt = blockIdx.x;                 // 0..1
    const int mt = blockIdx.y;                 // 0..1
    const int bn = blockIdx.z;                 // 0..2047

    const float* Ab = x  + (size_t)(bn * 256 + mt * 128) * CIN;  // [128][64]
    const float* Bb = w1 + (size_t)(dt * 128) * CIN;             // [128][64]

    float acc[8][8];
#pragma unroll
    for (int i = 0; i < 8; i++)
#pragma unroll
        for (int j = 0; j < 8; j++) acc[i][j] = 0.f;

#pragma unroll
    for (int kc = 0; kc < CIN; kc += 32) {
        __syncthreads();
#pragma unroll
        for (int it = 0; it < 4; it++) {
            int f = tid + it * 256;            // 1024 float4 per tile
            int r = f >> 3, c4 = f & 7;
            float4 va = *(const float4*)(Ab + (size_t)r * CIN + kc + c4 * 4);
            asT[(c4*4+0)*KP + r] = va.x;
            asT[(c4*4+1)*KP + r] = va.y;
            asT[(c4*4+2)*KP + r] = va.z;
            asT[(c4*4+3)*KP + r] = va.w;
            float4 vb = *(const float4*)(Bb + (size_t)r * CIN + kc + c4 * 4);
            bsT[(c4*4+0)*KP + r] = vb.x;
            bsT[(c4*4+1)*KP + r] = vb.y;
            bsT[(c4*4+2)*KP + r] = vb.z;
            bsT[(c4*4+3)*KP + r] = vb.w;
        }
        __syncthreads();
#pragma unroll
        for (int k = 0; k < 32; k++) {
            float a[8], b[8];
            float4 t;
            t = *(const float4*)&asT[k*KP + ty*8];     a[0]=t.x; a[1]=t.y; a[2]=t.z; a[3]=t.w;
            t = *(const float4*)&asT[k*KP + ty*8 + 4]; a[4]=t.x; a[5]=t.y; a[6]=t.z; a[7]=t.w;
            t = *(const float4*)&bsT[k*KP + tx*8];     b[0]=t.x; b[1]=t.y; b[2]=t.z; b[3]=t.w;
            t = *(const float4*)&bsT[k*KP + tx*8 + 4]; b[4]=t.x; b[5]=t.y; b[6]=t.z; b[7]=t.w;
#pragma unroll
            for (int i = 0; i < 8; i++)
#pragma unroll
                for (int j = 0; j < 8; j++)
                    acc[i][j] = fmaf(a[i], b[j], acc[i][j]);
        }
    }

    // local max over this thread's 8 m rows, add bias (max(s)+b == max(s+b))
    float lm[8];
#pragma unroll
    for (int j = 0; j < 8; j++) {
        float m = acc[0][j];
#pragma unroll
        for (int i = 1; i < 8; i++) m = fmaxf(m, acc[i][j]);
        lm[j] = m + b1[dt*128 + tx*8 + j];
    }

    // cross-thread max over the 16 m-tile groups (reuse smem)
    __syncthreads();
    float* red = s;                            // [16][128]
#pragma unroll
    for (int j = 0; j < 8; j++) red[ty*128 + tx*8 + j] = lm[j];
    __syncthreads();
    if (tid < 128) {
        float m = red[tid];
#pragma unroll
        for (int t = 1; t < 16; t++) m = fmaxf(m, red[t*128 + tid]);
        g_zpart[(size_t)(bn*2 + mt)*CMID + dt*128 + tid] = m;
    }
}

// ---------------------------------------------------------------------------
// K2: v[bn,o] = sum_d max(zpart0, zpart1)[bn,d] * w2[o, 64+d]
//     tiles 64x64, K=256 chunks of 32, 4x4 thread tiles.
// ---------------------------------------------------------------------------
__global__ __launch_bounds__(256)
void k2_vgemm(const float* __restrict__ w2)
{
    __shared__ float aT[32 * K2P];
    __shared__ float bT[32 * K2P];

    const int tid = threadIdx.x;
    const int tx = tid & 15, ty = tid >> 4;
    const int o0  = blockIdx.x * 64;           // 0..3
    const int bn0 = blockIdx.y * 64;           // 0..31

    float acc[4][4];
#pragma unroll
    for (int i = 0; i < 4; i++)
#pragma unroll
        for (int j = 0; j < 4; j++) acc[i][j] = 0.f;

    for (int kc = 0; kc < CMID; kc += 32) {
        __syncthreads();
#pragma unroll
        for (int it = 0; it < 8; it++) {
            int l = tid + it * 256;            // 2048 elems per tile
            int r = l >> 5, k = l & 31;
            float p0 = g_zpart[(size_t)(bn0 + r) * (2*CMID) + (kc + k)];
            float p1 = g_zpart[(size_t)(bn0 + r) * (2*CMID) + CMID + (kc + k)];
            aT[k * K2P + r] = fmaxf(p0, p1);
            bT[k * K2P + r] = w2[(size_t)(o0 + r) * W2P + CIN + kc + k];
        }
        __syncthreads();
#pragma unroll
        for (int k = 0; k < 32; k++) {
            float a[4], b[4];
#pragma unroll
            for (int i = 0; i < 4; i++) a[i] = aT[k*K2P + ty*4 + i];
#pragma unroll
            for (int j = 0; j < 4; j++) b[j] = bT[k*K2P + tx*4 + j];
#pragma unroll
            for (int i = 0; i < 4; i++)
#pragma unroll
                for (int j = 0; j < 4; j++)
                    acc[i][j] = fmaf(a[i], b[j], acc[i][j]);
        }
    }
#pragma unroll
    for (int i = 0; i < 4; i++)
#pragma unroll
        for (int j = 0; j < 4; j++)
            g_v[(size_t)(bn0 + ty*4 + i) * COUT + o0 + tx*4 + j] = acc[i][j];
}

// ---------------------------------------------------------------------------
// K3: out[row,o] = x[row,:] @ w2a[o,:]^T + v[row>>8, o]
//     rows = bn*256 + m (524288 total), tiles 128x128, K=64.
// ---------------------------------------------------------------------------
__global__ __launch_bounds__(256, 2)
void k3_gemm_out(const float* __restrict__ x, const float* __restrict__ w2,
                 float* __restrict__ out)
{
    __shared__ float s[2 * 32 * KP];
    float* asT = s;
    float* bsT = s + 32 * KP;

    const int tid = threadIdx.x;
    const int tx = tid & 15, ty = tid >> 4;
    const int o0 = blockIdx.x * 128;           // 0..1
    const int r0 = blockIdx.y * 128;           // 0..4095 tiles
    const int bn = r0 >> 8;                    // 128 | 256 so whole tile shares bn

    const float* Ab = x + (size_t)r0 * CIN;

    float acc[8][8];
#pragma unroll
    for (int i = 0; i < 8; i++)
#pragma unroll
        for (int j = 0; j < 8; j++) acc[i][j] = 0.f;

#pragma unroll
    for (int kc = 0; kc < CIN; kc += 32) {
        __syncthreads();
#pragma unroll
        for (int it = 0; it < 4; it++) {
            int f = tid + it * 256;
            int r = f >> 3, c4 = f & 7;
            float4 va = *(const float4*)(Ab + (size_t)r * CIN + kc + c4 * 4);
            asT[(c4*4+0)*KP + r] = va.x;
            asT[(c4*4+1)*KP + r] = va.y;
            asT[(c4*4+2)*KP + r] = va.z;
            asT[(c4*4+3)*KP + r] = va.w;
            float4 vb = *(const float4*)(w2 + (size_t)(o0 + r) * W2P + kc + c4 * 4);
            bsT[(c4*4+0)*KP + r] = vb.x;
            bsT[(c4*4+1)*KP + r] = vb.y;
            bsT[(c4*4+2)*KP + r] = vb.z;
            bsT[(c4*4+3)*KP + r] = vb.w;
        }
        __syncthreads();
#pragma unroll
        for (int k = 0; k < 32; k++) {
            float a[8], b[8];
            float4 t;
            t = *(const float4*)&asT[k*KP + ty*8];     a[0]=t.x; a[1]=t.y; a[2]=t.z; a[3]=t.w;
            t = *(const float4*)&asT[k*KP + ty*8 + 4]; a[4]=t.x; a[5]=t.y; a[6]=t.z; a[7]=t.w;
            t = *(const float4*)&bsT[k*KP + tx*8];     b[0]=t.x; b[1]=t.y; b[2]=t.z; b[3]=t.w;
            t = *(const float4*)&bsT[k*KP + tx*8 + 4]; b[4]=t.x; b[5]=t.y; b[6]=t.z; b[7]=t.w;
#pragma unroll
            for (int i = 0; i < 8; i++)
#pragma unroll
                for (int j = 0; j < 8; j++)
                    acc[i][j] = fmaf(a[i], b[j], acc[i][j]);
        }
    }

    // epilogue: add broadcast v row, vectorized stores
    const float* vrow = g_v + (size_t)bn * COUT + o0 + tx*8;
    float4 v0 = *(const float4*)vrow;
    float4 v1 = *(const float4*)(vrow + 4);
#pragma unroll
    for (int i = 0; i < 8; i++) {
        int row = r0 + ty*8 + i;
        float4 w0, w1v;
        w0.x = acc[i][0] + v0.x;  w0.y = acc[i][1] + v0.y;
        w0.z = acc[i][2] + v0.z;  w0.w = acc[i][3] + v0.w;
        w1v.x = acc[i][4] + v1.x; w1v.y = acc[i][5] + v1.y;
        w1v.z = acc[i][6] + v1.z; w1v.w = acc[i][7] + v1.w;
        *(float4*)(out + (size_t)row * COUT + o0 + tx*8)     = w0;
        *(float4*)(out + (size_t)row * COUT + o0 + tx*8 + 4) = w1v;
    }
}

// ---------------------------------------------------------------------------
extern "C" void kernel_launch(void* const* d_in, const int* in_sizes, int n_in,
                              void* d_out, int out_size) {
    const float* x  = (const float*)d_in[0];   // (8,256,256,64)
    const float* w1 = (const float*)d_in[1];   // (256,64)
    const float* b1 = (const float*)d_in[2];   // (256,)
    const float* w2 = (const float*)d_in[3];   // (256,320)
    // d_in[4] = dim_target (always 2) — ignored
    float* out = (float*)d_out;                // (8,256,256,256)

    dim3 g1(2, 2, BN_TOT);
    k1_gemm_max<<<g1, 256>>>(x, w1, b1);

    dim3 g2(COUT / 64, BN_TOT / 64);
    k2_vgemm<<<g2, 256>>>(w2);

    dim3 g3(COUT / 128, (BN_TOT * M_DIM) / 128);
    k3_gemm_out<<<g3, 256>>>(x, w2, out);
}

// round 2
// speedup vs baseline: 1.5282x; 1.5282x over previous
#include <cuda_runtime.h>
#include <cuda_bf16.h>

#define BN_TOT 2048          // B*N
#define M_DIM  256
#define CIN    64
#define CMID   256
#define COUT   256
#define W2P    320
#define K2P    65
#define SPITCH 40            // bf16 pitch for 32-wide k chunk (conflict-free for ldmatrix)

// ---- device-global scratch (no allocation allowed) ----
__device__ __nv_bfloat16 g_xh[BN_TOT * M_DIM * CIN];   // 67 MB
__device__ __nv_bfloat16 g_xl[BN_TOT * M_DIM * CIN];   // 67 MB
__device__ __nv_bfloat16 g_w1h[CMID * CIN];
__device__ __nv_bfloat16 g_w1l[CMID * CIN];
__device__ __nv_bfloat16 g_w2h[COUT * W2P];
__device__ __nv_bfloat16 g_w2l[COUT * W2P];
__device__ float g_zpart[BN_TOT * 2 * CMID];           // 4 MB
__device__ float g_v[BN_TOT * COUT];                   // 2 MB

// ---------------------------------------------------------------------------
// PTX helpers
// ---------------------------------------------------------------------------
__device__ __forceinline__ unsigned smem_u32(const void* p) {
    return (unsigned)__cvta_generic_to_shared(p);
}
__device__ __forceinline__ void ldm4(unsigned r[4], unsigned addr) {
    asm volatile("ldmatrix.sync.aligned.m8n8.x4.shared.b16 {%0,%1,%2,%3}, [%4];"
                 : "=r"(r[0]), "=r"(r[1]), "=r"(r[2]), "=r"(r[3]) : "r"(addr));
}
__device__ __forceinline__ void mma_bf16(float c[4], const unsigned a[4], const unsigned b[2]) {
    asm volatile("mma.sync.aligned.m16n8k16.row.col.f32.bf16.bf16.f32 "
                 "{%0,%1,%2,%3}, {%4,%5,%6,%7}, {%8,%9}, {%0,%1,%2,%3};"
                 : "+f"(c[0]), "+f"(c[1]), "+f"(c[2]), "+f"(c[3])
                 : "r"(a[0]), "r"(a[1]), "r"(a[2]), "r"(a[3]), "r"(b[0]), "r"(b[1]));
}

// ---------------------------------------------------------------------------
// Prepass: fp32 -> bf16 hi/lo split
// ---------------------------------------------------------------------------
__global__ void convert_x(const float* __restrict__ x) {
    int i = (blockIdx.x * 256 + threadIdx.x) * 4;
    float4 v = *(const float4*)(x + i);
    __nv_bfloat16 h0 = __float2bfloat16_rn(v.x);
    __nv_bfloat16 h1 = __float2bfloat16_rn(v.y);
    __nv_bfloat16 h2 = __float2bfloat16_rn(v.z);
    __nv_bfloat16 h3 = __float2bfloat16_rn(v.w);
    __nv_bfloat162* ph = (__nv_bfloat162*)(g_xh + i);
    ph[0] = __nv_bfloat162(h0, h1);
    ph[1] = __nv_bfloat162(h2, h3);
    __nv_bfloat162* pl = (__nv_bfloat162*)(g_xl + i);
    pl[0] = __nv_bfloat162(__float2bfloat16_rn(v.x - __bfloat162float(h0)),
                           __float2bfloat16_rn(v.y - __bfloat162float(h1)));
    pl[1] = __nv_bfloat162(__float2bfloat16_rn(v.z - __bfloat162float(h2)),
                           __float2bfloat16_rn(v.w - __bfloat162float(h3)));
}

__global__ void convert_w(const float* __restrict__ w1, const float* __restrict__ w2) {
    int i = blockIdx.x * 256 + threadIdx.x;   // 98304 total
    float v; __nv_bfloat16* ph; __nv_bfloat16* pl; int j;
    if (i < CMID * CIN) { j = i; v = w1[j]; ph = g_w1h; pl = g_w1l; }
    else { j = i - CMID * CIN; v = w2[j]; ph = g_w2h; pl = g_w2l; }
    __nv_bfloat16 h = __float2bfloat16_rn(v);
    ph[j] = h;
    pl[j] = __float2bfloat16_rn(v - __bfloat162float(h));
}

// ---------------------------------------------------------------------------
// Shared tile loader: 128 rows x 32 k (bf16) from row-major gmem (pitch in bf16)
// 256 threads, 2 iters of (64 rows x 4 uint4)
// ---------------------------------------------------------------------------
__device__ __forceinline__ void load_tile(__nv_bfloat16* sm, const __nv_bfloat16* g,
                                          int row0, int pitch, int kc, int tid) {
    int r = tid >> 2, kq = tid & 3;
#pragma unroll
    for (int it = 0; it < 2; it++) {
        int row = r + it * 64;
        uint4 v = *(const uint4*)(g + (size_t)(row0 + row) * pitch + kc + kq * 8);
        *(uint4*)(sm + row * SPITCH + kq * 8) = v;
    }
}

// ---------------------------------------------------------------------------
// MMA core: computes acc[4][4][4] for a 128x128 tile, K=64, 3-term bf16 split.
// A: rows (pitch pa), B: rows (pitch pb). Shared arrays passed in.
// ---------------------------------------------------------------------------
__device__ __forceinline__ void mma_tile(
    float acc[4][4][4],
    const __nv_bfloat16* gAh, const __nv_bfloat16* gAl, int rowA, int pa,
    const __nv_bfloat16* gBh, const __nv_bfloat16* gBl, int rowB, int pb,
    __nv_bfloat16* sAh, __nv_bfloat16* sAl, __nv_bfloat16* sBh, __nv_bfloat16* sBl,
    int tid)
{
    const int lane = tid & 31, warp = tid >> 5;
    const int warp_m = warp >> 2, warp_n = warp & 3;
    const int lrow = lane & 15, lkh = (lane >> 4) * 8;

#pragma unroll
    for (int kc = 0; kc < CIN; kc += 32) {
        __syncthreads();
        load_tile(sAh, gAh, rowA, pa, kc, tid);
        load_tile(sAl, gAl, rowA, pa, kc, tid);
        load_tile(sBh, gBh, rowB, pb, kc, tid);
        load_tile(sBl, gBl, rowB, pb, kc, tid);
        __syncthreads();
#pragma unroll
        for (int ks = 0; ks < 32; ks += 16) {
            unsigned afh[4][4], afl[4][4];
#pragma unroll
            for (int mi = 0; mi < 4; mi++) {
                int rr = warp_m * 64 + mi * 16 + lrow;
                ldm4(afh[mi], smem_u32(sAh + rr * SPITCH + ks + lkh));
                ldm4(afl[mi], smem_u32(sAl + rr * SPITCH + ks + lkh));
            }
            unsigned bfh[4][2], bfl[4][2];
#pragma unroll
            for (int np = 0; np < 2; np++) {
                int rr = warp_n * 32 + np * 16 + lrow;
                unsigned t[4];
                ldm4(t, smem_u32(sBh + rr * SPITCH + ks + lkh));
                bfh[2*np][0] = t[0]; bfh[2*np+1][0] = t[1];
                bfh[2*np][1] = t[2]; bfh[2*np+1][1] = t[3];
                ldm4(t, smem_u32(sBl + rr * SPITCH + ks + lkh));
                bfl[2*np][0] = t[0]; bfl[2*np+1][0] = t[1];
                bfl[2*np][1] = t[2]; bfl[2*np+1][1] = t[3];
            }
#pragma unroll
            for (int mi = 0; mi < 4; mi++)
#pragma unroll
                for (int ni = 0; ni < 4; ni++) {
                    mma_bf16(acc[mi][ni], afh[mi], bfh[ni]);
                    mma_bf16(acc[mi][ni], afh[mi], bfl[ni]);
                    mma_bf16(acc[mi][ni], afl[mi], bfh[ni]);
                }
        }
    }
}

// ---------------------------------------------------------------------------
// K1: z = x @ w1^T over 128m x 128d, then max over m -> g_zpart (+bias)
// ---------------------------------------------------------------------------
__global__ __launch_bounds__(256, 1)
void k1_mma_max(const float* __restrict__ b1)
{
    __shared__ __nv_bfloat16 sAh[128*SPITCH], sAl[128*SPITCH];
    __shared__ __nv_bfloat16 sBh[128*SPITCH], sBl[128*SPITCH];
    __shared__ float smax[2][128];

    const int tid = threadIdx.x;
    const int lane = tid & 31, warp = tid >> 5;
    const int warp_m = warp >> 2, warp_n = warp & 3;
    const int dt = blockIdx.x, mt = blockIdx.y, bn = blockIdx.z;

    float acc[4][4][4];
#pragma unroll
    for (int mi = 0; mi < 4; mi++)
#pragma unroll
        for (int ni = 0; ni < 4; ni++)
#pragma unroll
            for (int c = 0; c < 4; c++) acc[mi][ni][c] = 0.f;

    mma_tile(acc, g_xh, g_xl, bn * 256 + mt * 128, CIN,
                  g_w1h, g_w1l, dt * 128, CIN,
                  sAh, sAl, sBh, sBl, tid);

    // max over m within fragments, then lanes, then warps
#pragma unroll
    for (int ni = 0; ni < 4; ni++) {
        float m0 = fmaxf(acc[0][ni][0], acc[0][ni][2]);
        float m1 = fmaxf(acc[0][ni][1], acc[0][ni][3]);
#pragma unroll
        for (int mi = 1; mi < 4; mi++) {
            m0 = fmaxf(m0, fmaxf(acc[mi][ni][0], acc[mi][ni][2]));
            m1 = fmaxf(m1, fmaxf(acc[mi][ni][1], acc[mi][ni][3]));
        }
#pragma unroll
        for (int off = 4; off < 32; off <<= 1) {
            m0 = fmaxf(m0, __shfl_xor_sync(0xffffffffu, m0, off));
            m1 = fmaxf(m1, __shfl_xor_sync(0xffffffffu, m1, off));
        }
        if (lane < 4) {
            int col = warp_n * 32 + ni * 8 + lane * 2;
            smax[warp_m][col]     = m0;
            smax[warp_m][col + 1] = m1;
        }
    }
    __syncthreads();
    if (tid < 128) {
        float m = fmaxf(smax[0][tid], smax[1][tid]) + b1[dt * 128 + tid];
        g_zpart[(size_t)(bn * 2 + mt) * CMID + dt * 128 + tid] = m;
    }
}

// ---------------------------------------------------------------------------
// K2: v = max(zpart0, zpart1) @ w2b^T (SIMT; tiny: 0.27 GFLOP)
// ---------------------------------------------------------------------------
__global__ __launch_bounds__(256)
void k2_vgemm(const float* __restrict__ w2)
{
    __shared__ float aT[32 * K2P];
    __shared__ float bT[32 * K2P];

    const int tid = threadIdx.x;
    const int tx = tid & 15, ty = tid >> 4;
    const int o0  = blockIdx.x * 64;
    const int bn0 = blockIdx.y * 64;

    float acc[4][4];
#pragma unroll
    for (int i = 0; i < 4; i++)
#pragma unroll
        for (int j = 0; j < 4; j++) acc[i][j] = 0.f;

    for (int kc = 0; kc < CMID; kc += 32) {
        __syncthreads();
#pragma unroll
        for (int it = 0; it < 8; it++) {
            int l = tid + it * 256;
            int r = l >> 5, k = l & 31;
            float p0 = g_zpart[(size_t)(bn0 + r) * (2*CMID) + (kc + k)];
            float p1 = g_zpart[(size_t)(bn0 + r) * (2*CMID) + CMID + (kc + k)];
            aT[k * K2P + r] = fmaxf(p0, p1);
            bT[k * K2P + r] = w2[(size_t)(o0 + r) * W2P + CIN + kc + k];
        }
        __syncthreads();
#pragma unroll
        for (int k = 0; k < 32; k++) {
            float a[4], b[4];
#pragma unroll
            for (int i = 0; i < 4; i++) a[i] = aT[k*K2P + ty*4 + i];
#pragma unroll
            for (int j = 0; j < 4; j++) b[j] = bT[k*K2P + tx*4 + j];
#pragma unroll
            for (int i = 0; i < 4; i++)
#pragma unroll
                for (int j = 0; j < 4; j++)
                    acc[i][j] = fmaf(a[i], b[j], acc[i][j]);
        }
    }
#pragma unroll
    for (int i = 0; i < 4; i++)
#pragma unroll
        for (int j = 0; j < 4; j++)
            g_v[(size_t)(bn0 + ty*4 + i) * COUT + o0 + tx*4 + j] = acc[i][j];
}

// ---------------------------------------------------------------------------
// K3: out = x @ w2a^T + v  (128row x 128col tiles)
// ---------------------------------------------------------------------------
__global__ __launch_bounds__(256, 1)
void k3_mma_out(float* __restrict__ out)
{
    __shared__ __nv_bfloat16 sAh[128*SPITCH], sAl[128*SPITCH];
    __shared__ __nv_bfloat16 sBh[128*SPITCH], sBl[128*SPITCH];

    const int tid = threadIdx.x;
    const int lane = tid & 31, warp = tid >> 5;
    const int warp_m = warp >> 2, warp_n = warp & 3;
    const int n0 = blockIdx.x * 128;
    const int r0 = blockIdx.y * 128;
    const int bn = r0 >> 8;

    float acc[4][4][4];
#pragma unroll
    for (int mi = 0; mi < 4; mi++)
#pragma unroll
        for (int ni = 0; ni < 4; ni++)
#pragma unroll
            for (int c = 0; c < 4; c++) acc[mi][ni][c] = 0.f;

    mma_tile(acc, g_xh, g_xl, r0, CIN,
                  g_w2h, g_w2l, n0, W2P,
                  sAh, sAl, sBh, sBl, tid);

    // epilogue: add broadcast v, float2 stores
#pragma unroll
    for (int ni = 0; ni < 4; ni++) {
        int col = n0 + warp_n * 32 + ni * 8 + (lane & 3) * 2;
        float2 vv = *(const float2*)(g_v + (size_t)bn * COUT + col);
#pragma unroll
        for (int mi = 0; mi < 4; mi++) {
            int row = r0 + warp_m * 64 + mi * 16 + (lane >> 2);
            float2 o0v, o1v;
            o0v.x = acc[mi][ni][0] + vv.x; o0v.y = acc[mi][ni][1] + vv.y;
            o1v.x = acc[mi][ni][2] + vv.x; o1v.y = acc[mi][ni][3] + vv.y;
            *(float2*)(out + (size_t)row * COUT + col)       = o0v;
            *(float2*)(out + (size_t)(row + 8) * COUT + col) = o1v;
        }
    }
}

// ---------------------------------------------------------------------------
extern "C" void kernel_launch(void* const* d_in, const int* in_sizes, int n_in,
                              void* d_out, int out_size) {
    const float* x  = (const float*)d_in[0];   // (8,256,256,64)
    const float* w1 = (const float*)d_in[1];   // (256,64)
    const float* b1 = (const float*)d_in[2];   // (256,)
    const float* w2 = (const float*)d_in[3];   // (256,320)
    float* out = (float*)d_out;                // (8,256,256,256)

    convert_x<<<(BN_TOT * M_DIM * CIN) / (256 * 4), 256>>>(x);
    convert_w<<<(CMID * CIN + COUT * W2P) / 256, 256>>>(w1, w2);

    dim3 g1(2, 2, BN_TOT);
    k1_mma_max<<<g1, 256>>>(b1);

    dim3 g2(COUT / 64, BN_TOT / 64);
    k2_vgemm<<<g2, 256>>>(w2);

    dim3 g3(COUT / 128, (BN_TOT * M_DIM) / 128);
    k3_mma_out<<<g3, 256>>>(out);
}

// round 4
// speedup vs baseline: 3.3174x; 2.1707x over previous
#include <cuda_runtime.h>
#include <cuda_fp16.h>
#include <cstdint>

#define BN_TOT 2048
#define M_DIM  256
#define CIN    64
#define CMID   256
#define COUT   256
#define W2P    320
#define K2P    65
#define AP     72          // fp16 smem pitch: 144B rows -> ldmatrix 8-row group hits banks 0,4,..28

// device scratch (no allocation allowed)
__device__ float g_zmax[BN_TOT * CMID];   // 2 MB
__device__ float g_v[BN_TOT * COUT];      // 2 MB

// ---------------- PTX helpers ----------------
__device__ __forceinline__ unsigned smem_u32(const void* p) {
    return (unsigned)__cvta_generic_to_shared(p);
}
__device__ __forceinline__ void ldm4(unsigned r[4], unsigned addr) {
    asm volatile("ldmatrix.sync.aligned.m8n8.x4.shared.b16 {%0,%1,%2,%3}, [%4];"
                 : "=r"(r[0]), "=r"(r[1]), "=r"(r[2]), "=r"(r[3]) : "r"(addr));
}
__device__ __forceinline__ void mma_f16(float c[4], const unsigned a[4], const unsigned b[2]) {
    asm volatile("mma.sync.aligned.m16n8k16.row.col.f32.f16.f16.f32 "
                 "{%0,%1,%2,%3}, {%4,%5,%6,%7}, {%8,%9}, {%0,%1,%2,%3};"
                 : "+f"(c[0]), "+f"(c[1]), "+f"(c[2]), "+f"(c[3])
                 : "r"(a[0]), "r"(a[1]), "r"(a[2]), "r"(a[3]), "r"(b[0]), "r"(b[1]));
}

// ---------------------------------------------------------------------------
// Load 128 rows x 64 fp32 from gmem, convert to fp16, store to smem pitch AP.
// 256 threads x 4 iters; each thread: 32B gmem -> 16B smem, fully coalesced.
// ---------------------------------------------------------------------------
__device__ __forceinline__ void load_conv(__half* sm, const float* __restrict__ g,
                                          int row0, int pitch, int tid) {
#pragma unroll
    for (int it = 0; it < 4; it++) {
        int idx = it * 256 + tid;          // 0..1023
        int row = idx >> 3, q = idx & 7;
        const float* p = g + (size_t)(row0 + row) * pitch + q * 8;
        float4 v0 = *(const float4*)p;
        float4 v1 = *(const float4*)(p + 4);
        __half2 h0 = __halves2half2(__float2half_rn(v0.x), __float2half_rn(v0.y));
        __half2 h1 = __halves2half2(__float2half_rn(v0.z), __float2half_rn(v0.w));
        __half2 h2 = __halves2half2(__float2half_rn(v1.x), __float2half_rn(v1.y));
        __half2 h3 = __halves2half2(__float2half_rn(v1.z), __float2half_rn(v1.w));
        uint4 u;
        u.x = *(unsigned*)&h0; u.y = *(unsigned*)&h1;
        u.z = *(unsigned*)&h2; u.w = *(unsigned*)&h3;
        *(uint4*)(sm + row * AP + q * 8) = u;
    }
}

// ---------------------------------------------------------------------------
// Warp-level 128x128xK64 MMA core. warp tile = 32m x 64n.
// acc[2][8][4]. A rows = m, B rows = n (both k-major pitch AP).
// ---------------------------------------------------------------------------
__device__ __forceinline__ void mma_core(float acc[2][8][4],
                                         const __half* sA, const __half* sB,
                                         int warp_m, int warp_n, int lane) {
    const int lrow = lane & 15, lkh = (lane >> 4) * 8;
#pragma unroll
    for (int ks = 0; ks < 64; ks += 16) {
        unsigned af[2][4];
#pragma unroll
        for (int mi = 0; mi < 2; mi++)
            ldm4(af[mi], smem_u32(sA + (warp_m * 32 + mi * 16 + lrow) * AP + ks + lkh));
        unsigned bf[8][2];
#pragma unroll
        for (int np = 0; np < 4; np++) {
            unsigned t[4];
            ldm4(t, smem_u32(sB + (warp_n * 64 + np * 16 + lrow) * AP + ks + lkh));
            bf[2*np][0]   = t[0]; bf[2*np+1][0] = t[1];
            bf[2*np][1]   = t[2]; bf[2*np+1][1] = t[3];
        }
#pragma unroll
        for (int mi = 0; mi < 2; mi++)
#pragma unroll
            for (int ni = 0; ni < 8; ni++)
                mma_f16(acc[mi][ni], af[mi], bf[ni]);
    }
}

// ---------------------------------------------------------------------------
// K1: per (dt, bn): z = x @ w1^T over full 256 m (2 phases), max over m,
//     + bias -> g_zmax
// ---------------------------------------------------------------------------
__global__ void __launch_bounds__(256)
k1_mma_max(const float* __restrict__ x, const float* __restrict__ w1,
           const float* __restrict__ b1)
{
    __shared__ __align__(16) __half sA[128 * AP];
    __shared__ __align__(16) __half sB[128 * AP];
    __shared__ float smax[4][128];

    const int tid = threadIdx.x;
    const int lane = tid & 31, w = tid >> 5;
    const int warp_m = w >> 1, warp_n = w & 1;
    const int dt = blockIdx.x, bn = blockIdx.y;

    smax[tid >> 7][tid & 127] = -3.4e38f;
    smax[2 + (tid >> 7)][tid & 127] = -3.4e38f;

    load_conv(sB, w1, dt * 128, CIN, tid);

#pragma unroll
    for (int mt = 0; mt < 2; mt++) {
        __syncthreads();                   // prior phase's smem reads done
        load_conv(sA, x, bn * 256 + mt * 128, CIN, tid);
        __syncthreads();

        float acc[2][8][4];
#pragma unroll
        for (int mi = 0; mi < 2; mi++)
#pragma unroll
            for (int ni = 0; ni < 8; ni++)
#pragma unroll
                for (int c = 0; c < 4; c++) acc[mi][ni][c] = 0.f;

        mma_core(acc, sA, sB, warp_m, warp_n, lane);

        // reduce max over m: fragments -> lanes (rows live in lane>>2)
#pragma unroll
        for (int ni = 0; ni < 8; ni++) {
            float m0 = fmaxf(fmaxf(acc[0][ni][0], acc[0][ni][2]),
                             fmaxf(acc[1][ni][0], acc[1][ni][2]));
            float m1 = fmaxf(fmaxf(acc[0][ni][1], acc[0][ni][3]),
                             fmaxf(acc[1][ni][1], acc[1][ni][3]));
#pragma unroll
            for (int off = 4; off < 32; off <<= 1) {
                m0 = fmaxf(m0, __shfl_xor_sync(0xffffffffu, m0, off));
                m1 = fmaxf(m1, __shfl_xor_sync(0xffffffffu, m1, off));
            }
            if (lane < 4) {
                int col = warp_n * 64 + ni * 8 + lane * 2;
                smax[warp_m][col]     = fmaxf(smax[warp_m][col], m0);
                smax[warp_m][col + 1] = fmaxf(smax[warp_m][col + 1], m1);
            }
        }
    }

    __syncthreads();
    if (tid < 128) {
        float m = fmaxf(fmaxf(smax[0][tid], smax[1][tid]),
                        fmaxf(smax[2][tid], smax[3][tid]));
        g_zmax[(size_t)bn * CMID + dt * 128 + tid] = m + b1[dt * 128 + tid];
    }
}

// ---------------------------------------------------------------------------
// K2: v = zmax @ w2b^T (SIMT, tiny, fp32-exact)
// ---------------------------------------------------------------------------
__global__ __launch_bounds__(256)
void k2_vgemm(const float* __restrict__ w2)
{
    __shared__ float aT[32 * K2P];
    __shared__ float bT[32 * K2P];

    const int tid = threadIdx.x;
    const int tx = tid & 15, ty = tid >> 4;
    const int o0  = blockIdx.x * 64;
    const int bn0 = blockIdx.y * 64;

    float acc[4][4];
#pragma unroll
    for (int i = 0; i < 4; i++)
#pragma unroll
        for (int j = 0; j < 4; j++) acc[i][j] = 0.f;

    for (int kc = 0; kc < CMID; kc += 32) {
        __syncthreads();
#pragma unroll
        for (int it = 0; it < 8; it++) {
            int l = tid + it * 256;
            int r = l >> 5, k = l & 31;
            aT[k * K2P + r] = g_zmax[(size_t)(bn0 + r) * CMID + kc + k];
            bT[k * K2P + r] = w2[(size_t)(o0 + r) * W2P + CIN + kc + k];
        }
        __syncthreads();
#pragma unroll
        for (int k = 0; k < 32; k++) {
            float a[4], b[4];
#pragma unroll
            for (int i = 0; i < 4; i++) a[i] = aT[k * K2P + ty * 4 + i];
#pragma unroll
            for (int j = 0; j < 4; j++) b[j] = bT[k * K2P + tx * 4 + j];
#pragma unroll
            for (int i = 0; i < 4; i++)
#pragma unroll
                for (int j = 0; j < 4; j++)
                    acc[i][j] = fmaf(a[i], b[j], acc[i][j]);
        }
    }
#pragma unroll
    for (int i = 0; i < 4; i++)
#pragma unroll
        for (int j = 0; j < 4; j++)
            g_v[(size_t)(bn0 + ty * 4 + i) * COUT + o0 + tx * 4 + j] = acc[i][j];
}

// ---------------------------------------------------------------------------
// K3: per (nt, bn): out = x @ w2a^T + v, 2 row phases
// ---------------------------------------------------------------------------
__global__ void __launch_bounds__(256)
k3_mma_out(const float* __restrict__ x, const float* __restrict__ w2,
           float* __restrict__ out)
{
    __shared__ __align__(16) __half sA[128 * AP];
    __shared__ __align__(16) __half sB[128 * AP];
    __shared__ float sv[128];

    const int tid = threadIdx.x;
    const int lane = tid & 31, w = tid >> 5;
    const int warp_m = w >> 1, warp_n = w & 1;
    const int nt = blockIdx.x, bn = blockIdx.y;

    if (tid < 128) sv[tid] = g_v[(size_t)bn * COUT + nt * 128 + tid];

    load_conv(sB, w2, nt * 128, W2P, tid);   // w2a = first 64 cols of pitch-320 rows

#pragma unroll
    for (int rt = 0; rt < 2; rt++) {
        const int r0 = bn * 256 + rt * 128;
        __syncthreads();
        load_conv(sA, x, r0, CIN, tid);
        __syncthreads();

        float acc[2][8][4];
#pragma unroll
        for (int mi = 0; mi < 2; mi++)
#pragma unroll
            for (int ni = 0; ni < 8; ni++)
#pragma unroll
                for (int c = 0; c < 4; c++) acc[mi][ni][c] = 0.f;

        mma_core(acc, sA, sB, warp_m, warp_n, lane);

        // epilogue: add broadcast v, float2 stores
#pragma unroll
        for (int ni = 0; ni < 8; ni++) {
            int col = nt * 128 + warp_n * 64 + ni * 8 + (lane & 3) * 2;
            float2 vv = *(const float2*)(sv + warp_n * 64 + ni * 8 + (lane & 3) * 2);
#pragma unroll
            for (int mi = 0; mi < 2; mi++) {
                int row = r0 + warp_m * 32 + mi * 16 + (lane >> 2);
                float2 o0v, o1v;
                o0v.x = acc[mi][ni][0] + vv.x; o0v.y = acc[mi][ni][1] + vv.y;
                o1v.x = acc[mi][ni][2] + vv.x; o1v.y = acc[mi][ni][3] + vv.y;
                *(float2*)(out + (size_t)row * COUT + col)       = o0v;
                *(float2*)(out + (size_t)(row + 8) * COUT + col) = o1v;
            }
        }
    }
}

// ---------------------------------------------------------------------------
extern "C" void kernel_launch(void* const* d_in, const int* in_sizes, int n_in,
                              void* d_out, int out_size) {
    const float* x  = (const float*)d_in[0];   // (8,256,256,64)
    const float* w1 = (const float*)d_in[1];   // (256,64)
    const float* b1 = (const float*)d_in[2];   // (256,)
    const float* w2 = (const float*)d_in[3];   // (256,320)
    float* out = (float*)d_out;                // (8,256,256,256)

    dim3 g1(2, BN_TOT);
    k1_mma_max<<<g1, 256>>>(x, w1, b1);

    dim3 g2(COUT / 64, BN_TOT / 64);
    k2_vgemm<<<g2, 256>>>(w2);

    dim3 g3(2, BN_TOT);
    k3_mma_out<<<g3, 256>>>(x, w2, out);
}